// round 6
// baseline (speedup 1.0000x reference)
#include <cuda_runtime.h>
#include <cuda_bf16.h>
#include <cstdint>

using bf16 = __nv_bfloat16;

#define B_  32
#define S_  41
#define T_  41
#define H_  1024
#define V_  16384
#define G_  4096
#define TB_ 1312   // T_*B_

// output layout (flattened concat of reference return values, fp32)
#define OUT_DEC  0ull
#define OUT_HF   21495808ull
#define OUT_CF   21528576ull
#define OUT_ATTN 21561344ull

// ------------------------- device scratch (static, no allocs) -------------------------
__device__ bf16  g_enc_hi[TB_ * H_];
__device__ bf16  g_enc_lo[TB_ * H_];
__device__ bf16  g_Wk_hi[H_ * H_];
__device__ bf16  g_Wk_lo[H_ * H_];
__device__ bf16  g_Wq_hi[H_ * H_];
__device__ bf16  g_Wq_lo[H_ * H_];
__device__ bf16  g_Wx_hi[G_ * H_];
__device__ bf16  g_Wx_lo[G_ * H_];
__device__ bf16  g_Wrec_hi[G_ * 2 * H_];
__device__ bf16  g_Wrec_lo[G_ * 2 * H_];
__device__ bf16  g_Wout_bf[(size_t)V_ * H_];
__device__ bf16  g_X_hi[TB_ * H_];
__device__ bf16  g_X_lo[TB_ * H_];
__device__ float g_keys[TB_ * H_];
__device__ float g_gates_pre[(size_t)TB_ * G_];
__device__ float g_gates[B_ * G_];
__device__ float g_q[B_ * H_];
__device__ bf16  g_ctxh_hi[B_ * 2 * H_];   // per batch row: [ctx(1024) | h(1024)]
__device__ bf16  g_ctxh_lo[B_ * 2 * H_];
__device__ float g_h[2][B_ * H_];
__device__ float g_c[2][B_ * H_];
__device__ bf16  g_Hbf[TB_ * H_];
__device__ float g_bsum[G_];

__device__ __forceinline__ void split_bf(float v, bf16& hi, bf16& lo) {
    bf16 h = __float2bfloat16(v);
    hi = h;
    lo = __float2bfloat16(v - __bfloat162float(h));
}

// ------------------------- small prep kernels -------------------------
__global__ void k_cvt(const float* __restrict__ s, bf16* __restrict__ d, int n) {
    for (int i = blockIdx.x * blockDim.x + threadIdx.x; i < n; i += gridDim.x * blockDim.x)
        d[i] = __float2bfloat16(s[i]);
}

__global__ void k_cvt2(const float* __restrict__ s, bf16* __restrict__ hi, bf16* __restrict__ lo, int n) {
    for (int i = blockIdx.x * blockDim.x + threadIdx.x; i < n; i += gridDim.x * blockDim.x)
        split_bf(s[i], hi[i], lo[i]);
}

__global__ void k_cvt_wx(const float* __restrict__ Wih) {
    for (int i = blockIdx.x * blockDim.x + threadIdx.x; i < G_ * H_; i += gridDim.x * blockDim.x) {
        int n = i >> 10, k = i & 1023;
        split_bf(Wih[(size_t)n * 2048 + k], g_Wx_hi[i], g_Wx_lo[i]);
    }
}

__global__ void k_wrec(const float* __restrict__ Wih, const float* __restrict__ Whh) {
    for (int i = blockIdx.x * blockDim.x + threadIdx.x; i < G_ * 2 * H_; i += gridDim.x * blockDim.x) {
        int n = i >> 11, k = i & 2047;
        float v = (k < 1024) ? Wih[(size_t)n * 2048 + 1024 + k] : Whh[(size_t)n * 1024 + (k - 1024)];
        split_bf(v, g_Wrec_hi[i], g_Wrec_lo[i]);
    }
}

__global__ void k_bsum(const float* __restrict__ bih, const float* __restrict__ bhh) {
    int i = blockIdx.x * blockDim.x + threadIdx.x;
    if (i < G_) g_bsum[i] = bih[i] + bhh[i];
}

__global__ void k_init(const float* __restrict__ ehid) {
    int i = blockIdx.x * blockDim.x + threadIdx.x;
    if (i < B_ * H_) {
        float h = ehid[i];
        g_c[0][i] = 0.f;
        g_h[0][i] = h;
        int b = i >> 10, j = i & 1023;
        split_bf(h, g_ctxh_hi[b * 2048 + 1024 + j], g_ctxh_lo[b * 2048 + 1024 + j]);
    }
}

// NOTE: target_tensor is int32 on the wire (JAX downcasts int64 without x64 mode).
__global__ void k_gather(const float* __restrict__ emb, const int* __restrict__ tgt) {
    int r = blockIdx.x;             // r = t*32 + b
    int t = r >> 5, b = r & 31;
    int tok = (t == 0) ? 0 : tgt[b * 41 + (t - 1)];
    tok &= (V_ - 1);                // defensive: never fault on bad data
    const float* src = emb + (size_t)tok * H_;
    for (int h = threadIdx.x; h < H_; h += blockDim.x)
        split_bf(src[h], g_X_hi[(size_t)r * H_ + h], g_X_lo[(size_t)r * H_ + h]);
}

// ------------------------- MMA primitive -------------------------
__device__ __forceinline__ void mma16816(float* c, const uint32_t* a, const uint32_t* b) {
    asm volatile(
        "mma.sync.aligned.m16n8k16.row.col.f32.bf16.bf16.f32 "
        "{%0,%1,%2,%3}, {%4,%5,%6,%7}, {%8,%9}, {%0,%1,%2,%3};"
        : "+f"(c[0]), "+f"(c[1]), "+f"(c[2]), "+f"(c[3])
        : "r"(a[0]), "r"(a[1]), "r"(a[2]), "r"(a[3]), "r"(b[0]), "r"(b[1]));
}

// ---------- single-bf16 GEMM: C = A @ B^T (+bias); REMAP: row r=t*32+b -> out row b*T+t ----------
template <int WM, int WN, int NW, bool REMAP>
__global__ void __launch_bounds__(32 * NW)
k_gemm(const bf16* __restrict__ A, int lda,
       const bf16* __restrict__ B, int ldb,
       float* __restrict__ C, int ldc,
       const float* __restrict__ bias,
       int M, int N, int K) {
    const int lane = threadIdx.x & 31, warp = threadIdx.x >> 5;
    const int g = lane >> 2, tg = lane & 3;
    const int m0 = blockIdx.x * (16 * WM);
    const int n0 = blockIdx.y * (8 * WN * NW) + warp * (8 * WN);

    float acc[WM][WN][4];
#pragma unroll
    for (int i = 0; i < WM; i++)
#pragma unroll
        for (int j = 0; j < WN; j++)
#pragma unroll
            for (int q = 0; q < 4; q++) acc[i][j][q] = 0.f;

#pragma unroll 2
    for (int k0 = 0; k0 < K; k0 += 16) {
        uint32_t a[WM][4];
#pragma unroll
        for (int i = 0; i < WM; i++) {
            int r0 = m0 + 16 * i + g;
            int r1 = r0 + 8;
            int ra0 = (r0 < M) ? r0 : (M - 1);
            int ra1 = (r1 < M) ? r1 : (M - 1);
            const uint32_t* p0 = reinterpret_cast<const uint32_t*>(A + (size_t)ra0 * lda + k0);
            const uint32_t* p1 = reinterpret_cast<const uint32_t*>(A + (size_t)ra1 * lda + k0);
            a[i][0] = (r0 < M) ? p0[tg]     : 0u;
            a[i][2] = (r0 < M) ? p0[tg + 4] : 0u;
            a[i][1] = (r1 < M) ? p1[tg]     : 0u;
            a[i][3] = (r1 < M) ? p1[tg + 4] : 0u;
        }
        uint32_t b[WN][2];
#pragma unroll
        for (int j = 0; j < WN; j++) {
            int n = n0 + 8 * j + g;
            const uint32_t* pb = reinterpret_cast<const uint32_t*>(B + (size_t)n * ldb + k0);
            b[j][0] = pb[tg];
            b[j][1] = pb[tg + 4];
        }
#pragma unroll
        for (int i = 0; i < WM; i++)
#pragma unroll
            for (int j = 0; j < WN; j++) mma16816(acc[i][j], a[i], b[j]);
    }

#pragma unroll
    for (int i = 0; i < WM; i++) {
        int r0 = m0 + 16 * i + g;
        int r1 = r0 + 8;
        size_t or0 = REMAP ? ((size_t)(r0 & 31) * T_ + (r0 >> 5)) : (size_t)r0;
        size_t or1 = REMAP ? ((size_t)(r1 & 31) * T_ + (r1 >> 5)) : (size_t)r1;
#pragma unroll
        for (int j = 0; j < WN; j++) {
            int c0 = n0 + 8 * j + 2 * tg;
            float v0 = acc[i][j][0], v1 = acc[i][j][1], v2 = acc[i][j][2], v3 = acc[i][j][3];
            if (bias) {
                float bb0 = bias[c0], bb1 = bias[c0 + 1];
                v0 += bb0; v1 += bb1; v2 += bb0; v3 += bb1;
            }
            if (r0 < M) { C[or0 * ldc + c0] = v0; C[or0 * ldc + c0 + 1] = v1; }
            if (r1 < M) { C[or1 * ldc + c0] = v2; C[or1 * ldc + c0 + 1] = v3; }
        }
    }
}

// --------------- split-bf16 GEMM (~fp32 precision): C = A @ B^T (+bias)(+Cinit) ---------------
// A = A_hi + A_lo, B = B_hi + B_lo; acc += ah*bh + ah*bl + al*bh
template <int WM, int WN, int NW>
__global__ void __launch_bounds__(32 * NW)
k_gemm2(const bf16* __restrict__ Ah, const bf16* __restrict__ Al, int lda,
        const bf16* __restrict__ Bh, const bf16* __restrict__ Bl, int ldb,
        float* __restrict__ C, int ldc,
        const float* __restrict__ bias, const float* __restrict__ cinit,
        int M, int N, int K) {
    const int lane = threadIdx.x & 31, warp = threadIdx.x >> 5;
    const int g = lane >> 2, tg = lane & 3;
    const int m0 = blockIdx.x * (16 * WM);
    const int n0 = blockIdx.y * (8 * WN * NW) + warp * (8 * WN);

    float acc[WM][WN][4];
#pragma unroll
    for (int i = 0; i < WM; i++)
#pragma unroll
        for (int j = 0; j < WN; j++)
#pragma unroll
            for (int q = 0; q < 4; q++) acc[i][j][q] = 0.f;

    for (int k0 = 0; k0 < K; k0 += 16) {
        uint32_t ah[WM][4], al[WM][4];
#pragma unroll
        for (int i = 0; i < WM; i++) {
            int r0 = m0 + 16 * i + g;
            int r1 = r0 + 8;
            int ra0 = (r0 < M) ? r0 : (M - 1);
            int ra1 = (r1 < M) ? r1 : (M - 1);
            const uint32_t* ph0 = reinterpret_cast<const uint32_t*>(Ah + (size_t)ra0 * lda + k0);
            const uint32_t* ph1 = reinterpret_cast<const uint32_t*>(Ah + (size_t)ra1 * lda + k0);
            const uint32_t* pl0 = reinterpret_cast<const uint32_t*>(Al + (size_t)ra0 * lda + k0);
            const uint32_t* pl1 = reinterpret_cast<const uint32_t*>(Al + (size_t)ra1 * lda + k0);
            ah[i][0] = (r0 < M) ? ph0[tg]     : 0u;
            ah[i][2] = (r0 < M) ? ph0[tg + 4] : 0u;
            ah[i][1] = (r1 < M) ? ph1[tg]     : 0u;
            ah[i][3] = (r1 < M) ? ph1[tg + 4] : 0u;
            al[i][0] = (r0 < M) ? pl0[tg]     : 0u;
            al[i][2] = (r0 < M) ? pl0[tg + 4] : 0u;
            al[i][1] = (r1 < M) ? pl1[tg]     : 0u;
            al[i][3] = (r1 < M) ? pl1[tg + 4] : 0u;
        }
        uint32_t bh[WN][2], bl[WN][2];
#pragma unroll
        for (int j = 0; j < WN; j++) {
            int n = n0 + 8 * j + g;
            const uint32_t* pbh = reinterpret_cast<const uint32_t*>(Bh + (size_t)n * ldb + k0);
            const uint32_t* pbl = reinterpret_cast<const uint32_t*>(Bl + (size_t)n * ldb + k0);
            bh[j][0] = pbh[tg];
            bh[j][1] = pbh[tg + 4];
            bl[j][0] = pbl[tg];
            bl[j][1] = pbl[tg + 4];
        }
#pragma unroll
        for (int i = 0; i < WM; i++)
#pragma unroll
            for (int j = 0; j < WN; j++) {
                mma16816(acc[i][j], ah[i], bh[j]);
                mma16816(acc[i][j], ah[i], bl[j]);
                mma16816(acc[i][j], al[i], bh[j]);
            }
    }

#pragma unroll
    for (int i = 0; i < WM; i++) {
        int r0 = m0 + 16 * i + g;
        int r1 = r0 + 8;
#pragma unroll
        for (int j = 0; j < WN; j++) {
            int c0 = n0 + 8 * j + 2 * tg;
            float v0 = acc[i][j][0], v1 = acc[i][j][1], v2 = acc[i][j][2], v3 = acc[i][j][3];
            if (bias) {
                float bb0 = bias[c0], bb1 = bias[c0 + 1];
                v0 += bb0; v1 += bb1; v2 += bb0; v3 += bb1;
            }
            if (cinit) {
                if (r0 < M) { v0 += cinit[(size_t)r0 * ldc + c0]; v1 += cinit[(size_t)r0 * ldc + c0 + 1]; }
                if (r1 < M) { v2 += cinit[(size_t)r1 * ldc + c0]; v3 += cinit[(size_t)r1 * ldc + c0 + 1]; }
            }
            if (r0 < M) { C[(size_t)r0 * ldc + c0] = v0; C[(size_t)r0 * ldc + c0 + 1] = v1; }
            if (r1 < M) { C[(size_t)r1 * ldc + c0] = v2; C[(size_t)r1 * ldc + c0 + 1] = v3; }
        }
    }
}

// ------------------------- attention (per step): scores, softmax, ctx -------------------------
__global__ void __launch_bounds__(256) k_attn(const float* __restrict__ enc,
                                              const float* __restrict__ Vw,
                                              const float* __restrict__ bV,
                                              float* __restrict__ out_attn, int t) {
    __shared__ float sq[H_], sv[H_], ssc[48];
    const int b = blockIdx.x, tid = threadIdx.x;
    const int warp = tid >> 5, lane = tid & 31;

    for (int i = tid; i < H_; i += 256) { sq[i] = g_q[b * H_ + i]; sv[i] = Vw[i]; }
    __syncthreads();

    for (int s = warp; s < S_; s += 8) {
        const float* kp = g_keys + ((size_t)b * S_ + s) * H_;
        float a = 0.f;
        for (int h = lane; h < H_; h += 32)
            a += tanhf(sq[h] + kp[h]) * sv[h];
#pragma unroll
        for (int o = 16; o; o >>= 1) a += __shfl_xor_sync(0xffffffffu, a, o);
        if (lane == 0) ssc[s] = a + bV[0];
    }
    __syncthreads();

    if (warp == 0) {
        float v0 = ssc[lane];
        float v1 = (lane < S_ - 32) ? ssc[lane + 32] : -INFINITY;
        float m = fmaxf(v0, v1);
#pragma unroll
        for (int o = 16; o; o >>= 1) m = fmaxf(m, __shfl_xor_sync(0xffffffffu, m, o));
        float e0 = expf(v0 - m);
        float e1 = (lane < S_ - 32) ? expf(v1 - m) : 0.f;
        float s = e0 + e1;
#pragma unroll
        for (int o = 16; o; o >>= 1) s += __shfl_xor_sync(0xffffffffu, s, o);
        float inv = 1.f / s;
        float w0 = e0 * inv;
        ssc[lane] = w0;
        out_attn[((size_t)b * T_ + t) * S_ + lane] = w0;
        if (lane < S_ - 32) {
            float w1 = e1 * inv;
            ssc[lane + 32] = w1;
            out_attn[((size_t)b * T_ + t) * S_ + lane + 32] = w1;
        }
    }
    __syncthreads();

    for (int h = tid; h < H_; h += 256) {
        float a = 0.f;
        const float* ep = enc + (size_t)b * S_ * H_ + h;
#pragma unroll 1
        for (int s = 0; s < S_; s++) a += ssc[s] * ep[(size_t)s * H_];
        split_bf(a, g_ctxh_hi[b * 2048 + h], g_ctxh_lo[b * 2048 + h]);
    }
}

// ------------------------- LSTM elementwise update -------------------------
__global__ void __launch_bounds__(256) k_update(int t) {
    int idx = blockIdx.x * blockDim.x + threadIdx.x;
    if (idx >= B_ * H_) return;
    int b = idx >> 10, j = idx & 1023;
    const float* gp = g_gates + (size_t)b * G_;
    float ig = 1.f / (1.f + expf(-gp[j]));
    float fg = 1.f / (1.f + expf(-gp[1024 + j]));
    float gg = tanhf(gp[2048 + j]);
    float og = 1.f / (1.f + expf(-gp[3072 + j]));
    int par = t & 1;
    float c = fg * g_c[par][idx] + ig * gg;
    float h = og * tanhf(c);
    g_c[par ^ 1][idx] = c;
    g_h[par ^ 1][idx] = h;
    split_bf(h, g_ctxh_hi[b * 2048 + 1024 + j], g_ctxh_lo[b * 2048 + 1024 + j]);
    g_Hbf[(size_t)(t * B_ + b) * H_ + j] = __float2bfloat16(h);
}

// ------------------------- in-place log-softmax over V per output row -------------------------
__global__ void __launch_bounds__(256) k_logsoftmax(float* __restrict__ out) {
    __shared__ float red[8];
    __shared__ float bc;
    const int r = blockIdx.x;            // row of out[OUT_DEC] : (b*T+t)
    float* x = out + OUT_DEC + (size_t)r * V_;
    const int tid = threadIdx.x, lane = tid & 31, warp = tid >> 5;

    float m = -INFINITY;
    for (int v = tid; v < V_; v += 256) m = fmaxf(m, x[v]);
#pragma unroll
    for (int o2 = 16; o2; o2 >>= 1) m = fmaxf(m, __shfl_xor_sync(0xffffffffu, m, o2));
    if (lane == 0) red[warp] = m;
    __syncthreads();
    if (tid == 0) {
        float mm = red[0];
#pragma unroll
        for (int w = 1; w < 8; w++) mm = fmaxf(mm, red[w]);
        bc = mm;
    }
    __syncthreads();
    m = bc;

    float s = 0.f;
    for (int v = tid; v < V_; v += 256) s += expf(x[v] - m);
#pragma unroll
    for (int o2 = 16; o2; o2 >>= 1) s += __shfl_xor_sync(0xffffffffu, s, o2);
    __syncthreads();
    if (lane == 0) red[warp] = s;
    __syncthreads();
    if (tid == 0) {
        float ss = 0.f;
#pragma unroll
        for (int w = 0; w < 8; w++) ss += red[w];
        bc = m + logf(ss);
    }
    __syncthreads();
    float ls = bc;

    for (int v = tid; v < V_; v += 256) x[v] -= ls;
}

// ------------------------- final state copy -------------------------
__global__ void __launch_bounds__(256) k_final(float* __restrict__ out) {
    int i = blockIdx.x * blockDim.x + threadIdx.x;
    if (i < B_ * H_) {
        out[OUT_HF + i] = g_h[1][i];
        out[OUT_CF + i] = g_c[1][i];
    }
}

// ------------------------- launch -------------------------
extern "C" void kernel_launch(void* const* d_in, const int* in_sizes, int n_in,
                              void* d_out, int out_size) {
    (void)in_sizes; (void)n_in; (void)out_size;
    const float* enc  = (const float*)d_in[0];
    const float* ehid = (const float*)d_in[1];
    const int*   tgt  = (const int*)d_in[2];
    const float* emb  = (const float*)d_in[3];
    const float* Wq   = (const float*)d_in[4];
    const float* bq   = (const float*)d_in[5];
    const float* Wk   = (const float*)d_in[6];
    const float* bk   = (const float*)d_in[7];
    const float* Vw   = (const float*)d_in[8];
    const float* bV   = (const float*)d_in[9];
    const float* Wih  = (const float*)d_in[10];
    const float* Whh  = (const float*)d_in[11];
    const float* bih  = (const float*)d_in[12];
    const float* bhh  = (const float*)d_in[13];
    const float* Wout = (const float*)d_in[14];
    const float* bout = (const float*)d_in[15];
    float* out = (float*)d_out;

    void *p_enc_hi, *p_enc_lo, *p_Wk_hi, *p_Wk_lo, *p_Wq_hi, *p_Wq_lo,
         *p_Wx_hi, *p_Wx_lo, *p_Wrec_hi, *p_Wrec_lo, *p_Wout,
         *p_X_hi, *p_X_lo, *p_keys, *p_gpre, *p_gates, *p_q,
         *p_ch_hi, *p_ch_lo, *p_Hbf, *p_bsum;
    cudaGetSymbolAddress(&p_enc_hi, g_enc_hi);
    cudaGetSymbolAddress(&p_enc_lo, g_enc_lo);
    cudaGetSymbolAddress(&p_Wk_hi, g_Wk_hi);
    cudaGetSymbolAddress(&p_Wk_lo, g_Wk_lo);
    cudaGetSymbolAddress(&p_Wq_hi, g_Wq_hi);
    cudaGetSymbolAddress(&p_Wq_lo, g_Wq_lo);
    cudaGetSymbolAddress(&p_Wx_hi, g_Wx_hi);
    cudaGetSymbolAddress(&p_Wx_lo, g_Wx_lo);
    cudaGetSymbolAddress(&p_Wrec_hi, g_Wrec_hi);
    cudaGetSymbolAddress(&p_Wrec_lo, g_Wrec_lo);
    cudaGetSymbolAddress(&p_Wout, g_Wout_bf);
    cudaGetSymbolAddress(&p_X_hi, g_X_hi);
    cudaGetSymbolAddress(&p_X_lo, g_X_lo);
    cudaGetSymbolAddress(&p_keys, g_keys);
    cudaGetSymbolAddress(&p_gpre, g_gates_pre);
    cudaGetSymbolAddress(&p_gates, g_gates);
    cudaGetSymbolAddress(&p_q, g_q);
    cudaGetSymbolAddress(&p_ch_hi, g_ctxh_hi);
    cudaGetSymbolAddress(&p_ch_lo, g_ctxh_lo);
    cudaGetSymbolAddress(&p_Hbf, g_Hbf);
    cudaGetSymbolAddress(&p_bsum, g_bsum);

    // prep
    k_cvt2<<<2048, 256>>>(enc, (bf16*)p_enc_hi, (bf16*)p_enc_lo, TB_ * H_);
    k_cvt2<<<1024, 256>>>(Wq, (bf16*)p_Wq_hi, (bf16*)p_Wq_lo, H_ * H_);
    k_cvt2<<<1024, 256>>>(Wk, (bf16*)p_Wk_hi, (bf16*)p_Wk_lo, H_ * H_);
    k_cvt<<<4096, 256>>>(Wout, (bf16*)p_Wout, V_ * H_);
    k_cvt_wx<<<4096, 256>>>(Wih);
    k_wrec<<<8192, 256>>>(Wih, Whh);
    k_bsum<<<16, 256>>>(bih, bhh);
    k_init<<<128, 256>>>(ehid);
    k_gather<<<TB_, 256>>>(emb, tgt);

    // hoisted GEMMs (split precision)
    {   // keys_proj = enc @ Wk^T + bk : [1312,1024]
        dim3 grid((TB_ + 63) / 64, H_ / 128);
        k_gemm2<4, 2, 8><<<grid, 256>>>((const bf16*)p_enc_hi, (const bf16*)p_enc_lo, H_,
                                        (const bf16*)p_Wk_hi, (const bf16*)p_Wk_lo, H_,
                                        (float*)p_keys, H_, bk, nullptr, TB_, H_, H_);
    }
    {   // gates_pre = X @ Wx^T + (bih+bhh) : [1312,4096]
        dim3 grid((TB_ + 63) / 64, G_ / 128);
        k_gemm2<4, 2, 8><<<grid, 256>>>((const bf16*)p_X_hi, (const bf16*)p_X_lo, H_,
                                        (const bf16*)p_Wx_hi, (const bf16*)p_Wx_lo, H_,
                                        (float*)p_gpre, G_, (const float*)p_bsum, nullptr, TB_, G_, H_);
    }

    // sequential decode
    for (int t = 0; t < T_; t++) {
        {   // q = h @ Wq^T + bq : [32,1024]
            dim3 grid(1, H_ / 128);
            k_gemm2<2, 2, 8><<<grid, 256>>>((const bf16*)p_ch_hi + H_, (const bf16*)p_ch_lo + H_, 2 * H_,
                                            (const bf16*)p_Wq_hi, (const bf16*)p_Wq_lo, H_,
                                            (float*)p_q, H_, bq, nullptr, B_, H_, H_);
        }
        k_attn<<<B_, 256>>>(enc, Vw, bV, out + OUT_ATTN, t);
        {   // gates = gates_pre[t] + [ctx|h] @ Wrec^T : [32,4096]
            dim3 grid(1, G_ / 128);
            k_gemm2<2, 2, 8><<<grid, 256>>>((const bf16*)p_ch_hi, (const bf16*)p_ch_lo, 2 * H_,
                                            (const bf16*)p_Wrec_hi, (const bf16*)p_Wrec_lo, 2 * H_,
                                            (float*)p_gates, G_, nullptr,
                                            (const float*)p_gpre + (size_t)t * B_ * G_,
                                            B_, G_, 2 * H_);
        }
        k_update<<<128, 256>>>(t);
    }

    {   // logits -> directly into out[OUT_DEC] at [b,t,:] via remap epilogue
        dim3 grid((TB_ + 63) / 64, V_ / 128);
        k_gemm<4, 2, 8, true><<<grid, 256>>>((const bf16*)p_Hbf, H_, (const bf16*)p_Wout, H_,
                                             out + OUT_DEC, V_, bout, TB_, V_, H_);
    }
    k_logsoftmax<<<TB_, 256>>>(out);
    k_final<<<128, 256>>>(out);
}

// round 7
// speedup vs baseline: 1.9544x; 1.9544x over previous
#include <cuda_runtime.h>
#include <cuda_bf16.h>
#include <cstdint>

using bf16 = __nv_bfloat16;

#define B_  32
#define S_  41
#define T_  41
#define H_  1024
#define V_  16384
#define G_  4096
#define NA_ 5120   // combined q(1024) + ghh(4096)
#define TB_ 1312   // T_*B_

// output layout (flattened concat of reference return values, fp32)
#define OUT_DEC  0ull
#define OUT_HF   21495808ull
#define OUT_CF   21528576ull
#define OUT_ATTN 21561344ull

// ------------------------- device scratch (static, no allocs) -------------------------
__device__ bf16  g_enc_hi[TB_ * H_];
__device__ bf16  g_enc_lo[TB_ * H_];
__device__ float g_encT[B_ * H_ * S_];          // enc transposed [b,h,s]
__device__ bf16  g_Wk_hi[H_ * H_];
__device__ bf16  g_Wk_lo[H_ * H_];
__device__ bf16  g_Wqhh_hi[NA_ * H_];           // rows 0..1023 = Wq; 1024..5119 = Whh
__device__ bf16  g_Wqhh_lo[NA_ * H_];
__device__ bf16  g_Wx_hi[G_ * H_];              // Wih[:, 0:1024]   (x part)
__device__ bf16  g_Wx_lo[G_ * H_];
__device__ bf16  g_Wc_hi[G_ * H_];              // Wih[:, 1024:2048] (ctx part)
__device__ bf16  g_Wc_lo[G_ * H_];
__device__ bf16  g_Wout_bf[(size_t)V_ * H_];
__device__ bf16  g_X_hi[TB_ * H_];
__device__ bf16  g_X_lo[TB_ * H_];
__device__ float g_keys[TB_ * H_];
__device__ float g_gates_pre[(size_t)TB_ * G_]; // X@Wx^T + bih + bhh
__device__ float g_qghh[B_ * NA_];              // per b: [q(1024) | h@Whh^T(4096)]
__device__ bf16  g_ctxh_hi[B_ * 2 * H_];        // per b: [ctx(1024) | h(1024)]
__device__ bf16  g_ctxh_lo[B_ * 2 * H_];
__device__ float g_h[2][B_ * H_];
__device__ float g_c[2][B_ * H_];
__device__ bf16  g_Hbf[TB_ * H_];
__device__ float g_bsum[G_];
__device__ float g_bA[NA_];                     // [bq | zeros]

__device__ __forceinline__ void split_bf(float v, bf16& hi, bf16& lo) {
    bf16 h = __float2bfloat16(v);
    hi = h;
    lo = __float2bfloat16(v - __bfloat162float(h));
}

// ------------------------- small prep kernels -------------------------
__global__ void k_cvt(const float* __restrict__ s, bf16* __restrict__ d, int n) {
    for (int i = blockIdx.x * blockDim.x + threadIdx.x; i < n; i += gridDim.x * blockDim.x)
        d[i] = __float2bfloat16(s[i]);
}

__global__ void k_cvt2(const float* __restrict__ s, bf16* __restrict__ hi, bf16* __restrict__ lo, int n) {
    for (int i = blockIdx.x * blockDim.x + threadIdx.x; i < n; i += gridDim.x * blockDim.x)
        split_bf(s[i], hi[i], lo[i]);
}

__global__ void k_wqhh(const float* __restrict__ Wq, const float* __restrict__ Whh) {
    for (int i = blockIdx.x * blockDim.x + threadIdx.x; i < NA_ * H_; i += gridDim.x * blockDim.x) {
        int n = i >> 10, k = i & 1023;
        float v = (n < 1024) ? Wq[(size_t)n * H_ + k] : Whh[(size_t)(n - 1024) * H_ + k];
        split_bf(v, g_Wqhh_hi[i], g_Wqhh_lo[i]);
    }
}

__global__ void k_cvt_wx(const float* __restrict__ Wih) {
    for (int i = blockIdx.x * blockDim.x + threadIdx.x; i < G_ * H_; i += gridDim.x * blockDim.x) {
        int n = i >> 10, k = i & 1023;
        split_bf(Wih[(size_t)n * 2048 + k], g_Wx_hi[i], g_Wx_lo[i]);
    }
}

__global__ void k_wc(const float* __restrict__ Wih) {
    for (int i = blockIdx.x * blockDim.x + threadIdx.x; i < G_ * H_; i += gridDim.x * blockDim.x) {
        int n = i >> 10, k = i & 1023;
        split_bf(Wih[(size_t)n * 2048 + 1024 + k], g_Wc_hi[i], g_Wc_lo[i]);
    }
}

__global__ void k_bias(const float* __restrict__ bih, const float* __restrict__ bhh,
                       const float* __restrict__ bq) {
    int i = blockIdx.x * blockDim.x + threadIdx.x;
    if (i < G_) g_bsum[i] = bih[i] + bhh[i];
    if (i < NA_) g_bA[i] = (i < H_) ? bq[i] : 0.f;
}

__global__ void k_init(const float* __restrict__ ehid) {
    int i = blockIdx.x * blockDim.x + threadIdx.x;
    if (i < B_ * H_) {
        float h = ehid[i];
        g_c[0][i] = 0.f;
        g_h[0][i] = h;
        int b = i >> 10, j = i & 1023;
        split_bf(h, g_ctxh_hi[b * 2048 + 1024 + j], g_ctxh_lo[b * 2048 + 1024 + j]);
    }
}

// NOTE: target_tensor is int32 on the wire (JAX downcasts int64 without x64 mode).
__global__ void k_gather(const float* __restrict__ emb, const int* __restrict__ tgt) {
    int r = blockIdx.x;             // r = t*32 + b
    int t = r >> 5, b = r & 31;
    int tok = (t == 0) ? 0 : tgt[b * 41 + (t - 1)];
    tok &= (V_ - 1);                // defensive: never fault on bad data
    const float* src = emb + (size_t)tok * H_;
    for (int h = threadIdx.x; h < H_; h += blockDim.x)
        split_bf(src[h], g_X_hi[(size_t)r * H_ + h], g_X_lo[(size_t)r * H_ + h]);
}

__global__ void k_transpose_enc(const float* __restrict__ enc) {
    int b = blockIdx.x;
    const float* src = enc + (size_t)b * S_ * H_;
    float* dst = g_encT + (size_t)b * H_ * S_;
    for (int i = threadIdx.x; i < S_ * H_; i += blockDim.x) {
        int s = i >> 10, h = i & 1023;
        dst[h * S_ + s] = src[i];
    }
}

// ------------------------- MMA primitive -------------------------
__device__ __forceinline__ void mma16816(float* c, const uint32_t* a, const uint32_t* b) {
    asm volatile(
        "mma.sync.aligned.m16n8k16.row.col.f32.bf16.bf16.f32 "
        "{%0,%1,%2,%3}, {%4,%5,%6,%7}, {%8,%9}, {%0,%1,%2,%3};"
        : "+f"(c[0]), "+f"(c[1]), "+f"(c[2]), "+f"(c[3])
        : "r"(a[0]), "r"(a[1]), "r"(a[2]), "r"(a[3]), "r"(b[0]), "r"(b[1]));
}

// ---------- single-bf16 GEMM: C = A @ B^T (+bias); REMAP: row r=t*32+b -> out row b*T+t ----------
template <int WM, int WN, int NW, bool REMAP>
__global__ void __launch_bounds__(32 * NW)
k_gemm(const bf16* __restrict__ A, int lda,
       const bf16* __restrict__ B, int ldb,
       float* __restrict__ C, int ldc,
       const float* __restrict__ bias,
       int M, int N, int K) {
    const int lane = threadIdx.x & 31, warp = threadIdx.x >> 5;
    const int g = lane >> 2, tg = lane & 3;
    const int m0 = blockIdx.x * (16 * WM);
    const int n0 = blockIdx.y * (8 * WN * NW) + warp * (8 * WN);

    float acc[WM][WN][4];
#pragma unroll
    for (int i = 0; i < WM; i++)
#pragma unroll
        for (int j = 0; j < WN; j++)
#pragma unroll
            for (int q = 0; q < 4; q++) acc[i][j][q] = 0.f;

#pragma unroll 2
    for (int k0 = 0; k0 < K; k0 += 16) {
        uint32_t a[WM][4];
#pragma unroll
        for (int i = 0; i < WM; i++) {
            int r0 = m0 + 16 * i + g;
            int r1 = r0 + 8;
            int ra0 = (r0 < M) ? r0 : (M - 1);
            int ra1 = (r1 < M) ? r1 : (M - 1);
            const uint32_t* p0 = reinterpret_cast<const uint32_t*>(A + (size_t)ra0 * lda + k0);
            const uint32_t* p1 = reinterpret_cast<const uint32_t*>(A + (size_t)ra1 * lda + k0);
            a[i][0] = (r0 < M) ? p0[tg]     : 0u;
            a[i][2] = (r0 < M) ? p0[tg + 4] : 0u;
            a[i][1] = (r1 < M) ? p1[tg]     : 0u;
            a[i][3] = (r1 < M) ? p1[tg + 4] : 0u;
        }
        uint32_t b[WN][2];
#pragma unroll
        for (int j = 0; j < WN; j++) {
            int n = n0 + 8 * j + g;
            const uint32_t* pb = reinterpret_cast<const uint32_t*>(B + (size_t)n * ldb + k0);
            b[j][0] = pb[tg];
            b[j][1] = pb[tg + 4];
        }
#pragma unroll
        for (int i = 0; i < WM; i++)
#pragma unroll
            for (int j = 0; j < WN; j++) mma16816(acc[i][j], a[i], b[j]);
    }

#pragma unroll
    for (int i = 0; i < WM; i++) {
        int r0 = m0 + 16 * i + g;
        int r1 = r0 + 8;
        size_t or0 = REMAP ? ((size_t)(r0 & 31) * T_ + (r0 >> 5)) : (size_t)r0;
        size_t or1 = REMAP ? ((size_t)(r1 & 31) * T_ + (r1 >> 5)) : (size_t)r1;
#pragma unroll
        for (int j = 0; j < WN; j++) {
            int c0 = n0 + 8 * j + 2 * tg;
            float v0 = acc[i][j][0], v1 = acc[i][j][1], v2 = acc[i][j][2], v3 = acc[i][j][3];
            if (bias) {
                float bb0 = bias[c0], bb1 = bias[c0 + 1];
                v0 += bb0; v1 += bb1; v2 += bb0; v3 += bb1;
            }
            if (r0 < M) { C[or0 * ldc + c0] = v0; C[or0 * ldc + c0 + 1] = v1; }
            if (r1 < M) { C[or1 * ldc + c0] = v2; C[or1 * ldc + c0 + 1] = v3; }
        }
    }
}

// --------------- split-bf16 GEMM (~fp32 precision): C = A @ B^T (+bias) ---------------
template <int WM, int WN, int NW>
__global__ void __launch_bounds__(32 * NW)
k_gemm2(const bf16* __restrict__ Ah, const bf16* __restrict__ Al, int lda,
        const bf16* __restrict__ Bh, const bf16* __restrict__ Bl, int ldb,
        float* __restrict__ C, int ldc,
        const float* __restrict__ bias,
        int M, int N, int K) {
    const int lane = threadIdx.x & 31, warp = threadIdx.x >> 5;
    const int g = lane >> 2, tg = lane & 3;
    const int m0 = blockIdx.x * (16 * WM);
    const int n0 = blockIdx.y * (8 * WN * NW) + warp * (8 * WN);

    float acc[WM][WN][4];
#pragma unroll
    for (int i = 0; i < WM; i++)
#pragma unroll
        for (int j = 0; j < WN; j++)
#pragma unroll
            for (int q = 0; q < 4; q++) acc[i][j][q] = 0.f;

#pragma unroll 2
    for (int k0 = 0; k0 < K; k0 += 16) {
        uint32_t ah[WM][4], al[WM][4];
#pragma unroll
        for (int i = 0; i < WM; i++) {
            int r0 = m0 + 16 * i + g;
            int r1 = r0 + 8;
            int ra0 = (r0 < M) ? r0 : (M - 1);
            int ra1 = (r1 < M) ? r1 : (M - 1);
            const uint32_t* ph0 = reinterpret_cast<const uint32_t*>(Ah + (size_t)ra0 * lda + k0);
            const uint32_t* ph1 = reinterpret_cast<const uint32_t*>(Ah + (size_t)ra1 * lda + k0);
            const uint32_t* pl0 = reinterpret_cast<const uint32_t*>(Al + (size_t)ra0 * lda + k0);
            const uint32_t* pl1 = reinterpret_cast<const uint32_t*>(Al + (size_t)ra1 * lda + k0);
            ah[i][0] = (r0 < M) ? ph0[tg]     : 0u;
            ah[i][2] = (r0 < M) ? ph0[tg + 4] : 0u;
            ah[i][1] = (r1 < M) ? ph1[tg]     : 0u;
            ah[i][3] = (r1 < M) ? ph1[tg + 4] : 0u;
            al[i][0] = (r0 < M) ? pl0[tg]     : 0u;
            al[i][2] = (r0 < M) ? pl0[tg + 4] : 0u;
            al[i][1] = (r1 < M) ? pl1[tg]     : 0u;
            al[i][3] = (r1 < M) ? pl1[tg + 4] : 0u;
        }
        uint32_t bh[WN][2], bl[WN][2];
#pragma unroll
        for (int j = 0; j < WN; j++) {
            int n = n0 + 8 * j + g;
            const uint32_t* pbh = reinterpret_cast<const uint32_t*>(Bh + (size_t)n * ldb + k0);
            const uint32_t* pbl = reinterpret_cast<const uint32_t*>(Bl + (size_t)n * ldb + k0);
            bh[j][0] = pbh[tg];
            bh[j][1] = pbh[tg + 4];
            bl[j][0] = pbl[tg];
            bl[j][1] = pbl[tg + 4];
        }
#pragma unroll
        for (int i = 0; i < WM; i++)
#pragma unroll
            for (int j = 0; j < WN; j++) {
                mma16816(acc[i][j], ah[i], bh[j]);
                mma16816(acc[i][j], ah[i], bl[j]);
                mma16816(acc[i][j], al[i], bh[j]);
            }
    }

#pragma unroll
    for (int i = 0; i < WM; i++) {
        int r0 = m0 + 16 * i + g;
        int r1 = r0 + 8;
#pragma unroll
        for (int j = 0; j < WN; j++) {
            int c0 = n0 + 8 * j + 2 * tg;
            float v0 = acc[i][j][0], v1 = acc[i][j][1], v2 = acc[i][j][2], v3 = acc[i][j][3];
            if (bias) {
                float bb0 = bias[c0], bb1 = bias[c0 + 1];
                v0 += bb0; v1 += bb1; v2 += bb0; v3 += bb1;
            }
            if (r0 < M) { C[(size_t)r0 * ldc + c0] = v0; C[(size_t)r0 * ldc + c0 + 1] = v1; }
            if (r1 < M) { C[(size_t)r1 * ldc + c0] = v2; C[(size_t)r1 * ldc + c0 + 1] = v3; }
        }
    }
}

// ------------------------- attention (per step): scores, softmax, ctx -------------------------
__global__ void __launch_bounds__(256) k_attn(const float* __restrict__ Vw,
                                              const float* __restrict__ bV,
                                              float* __restrict__ out_attn, int t) {
    __shared__ float sq[H_], sv[H_], ssc[48];
    const int b = blockIdx.x, tid = threadIdx.x;
    const int warp = tid >> 5, lane = tid & 31;

    for (int i = tid; i < H_; i += 256) { sq[i] = g_qghh[b * NA_ + i]; sv[i] = Vw[i]; }
    __syncthreads();

    for (int s = warp; s < S_; s += 8) {
        const float* kp = g_keys + ((size_t)b * S_ + s) * H_;
        float a = 0.f;
        for (int h = lane; h < H_; h += 32)
            a += tanhf(sq[h] + kp[h]) * sv[h];
#pragma unroll
        for (int o = 16; o; o >>= 1) a += __shfl_xor_sync(0xffffffffu, a, o);
        if (lane == 0) ssc[s] = a + bV[0];
    }
    __syncthreads();

    if (warp == 0) {
        float v0 = ssc[lane];
        float v1 = (lane < S_ - 32) ? ssc[lane + 32] : -INFINITY;
        float m = fmaxf(v0, v1);
#pragma unroll
        for (int o = 16; o; o >>= 1) m = fmaxf(m, __shfl_xor_sync(0xffffffffu, m, o));
        float e0 = expf(v0 - m);
        float e1 = (lane < S_ - 32) ? expf(v1 - m) : 0.f;
        float s = e0 + e1;
#pragma unroll
        for (int o = 16; o; o >>= 1) s += __shfl_xor_sync(0xffffffffu, s, o);
        float inv = 1.f / s;
        float w0 = e0 * inv;
        ssc[lane] = w0;
        out_attn[((size_t)b * T_ + t) * S_ + lane] = w0;
        if (lane < S_ - 32) {
            float w1 = e1 * inv;
            ssc[lane + 32] = w1;
            out_attn[((size_t)b * T_ + t) * S_ + lane + 32] = w1;
        }
    }
    __syncthreads();

    // ctx via transposed enc: contiguous 41-float rows per (b,h)
    for (int h = tid; h < H_; h += 256) {
        const float* ep = g_encT + ((size_t)b * H_ + h) * S_;
        float a = 0.f;
#pragma unroll
        for (int s = 0; s < S_; s++) a += ssc[s] * ep[s];
        split_bf(a, g_ctxh_hi[b * 2048 + h], g_ctxh_lo[b * 2048 + h]);
    }
}

// ---------------- fused gates(ctx part) + LSTM update ----------------
// grid 128 blocks; block bid owns j-range [bid*8, bid*8+8) across all 4 gate quadrants.
// warp w (0..7): gate quadrant qg = w>>1, m-half mh = w&1.
// Computes 16x8 tile of ctx @ Wc^T for rows (batches) mh*16..+16, cols qg*1024 + j0 .. +8.
__global__ void __launch_bounds__(256) k_gates(int t) {
    __shared__ float sg[32][33];
    const int tid = threadIdx.x, lane = tid & 31, warp = tid >> 5;
    const int g = lane >> 2, tg = lane & 3;
    const int j0 = blockIdx.x * 8;
    const int qg = warp >> 1, mh = warp & 1;
    const int m0 = mh * 16;
    const int ng = qg * 1024 + j0;          // global N row base for this warp

    float acc[4] = {0.f, 0.f, 0.f, 0.f};

    const int r0 = m0 + g, r1 = r0 + 8;     // batch rows (always < 32)
    const bf16* Ah0 = g_ctxh_hi + r0 * 2048;
    const bf16* Ah1 = g_ctxh_hi + r1 * 2048;
    const bf16* Al0 = g_ctxh_lo + r0 * 2048;
    const bf16* Al1 = g_ctxh_lo + r1 * 2048;
    const bf16* Bh = g_Wc_hi + (size_t)(ng + g) * H_;
    const bf16* Bl = g_Wc_lo + (size_t)(ng + g) * H_;

#pragma unroll 4
    for (int k0 = 0; k0 < H_; k0 += 16) {
        uint32_t ah[4], al[4], bh[2], bl[2];
        const uint32_t* ph0 = reinterpret_cast<const uint32_t*>(Ah0 + k0);
        const uint32_t* ph1 = reinterpret_cast<const uint32_t*>(Ah1 + k0);
        const uint32_t* pl0 = reinterpret_cast<const uint32_t*>(Al0 + k0);
        const uint32_t* pl1 = reinterpret_cast<const uint32_t*>(Al1 + k0);
        const uint32_t* pbh = reinterpret_cast<const uint32_t*>(Bh + k0);
        const uint32_t* pbl = reinterpret_cast<const uint32_t*>(Bl + k0);
        ah[0] = ph0[tg]; ah[2] = ph0[tg + 4];
        ah[1] = ph1[tg]; ah[3] = ph1[tg + 4];
        al[0] = pl0[tg]; al[2] = pl0[tg + 4];
        al[1] = pl1[tg]; al[3] = pl1[tg + 4];
        bh[0] = pbh[tg]; bh[1] = pbh[tg + 4];
        bl[0] = pbl[tg]; bl[1] = pbl[tg + 4];
        mma16816(acc, ah, bh);
        mma16816(acc, ah, bl);
        mma16816(acc, al, bh);
    }

    // epilogue: add gates_pre[t] + ghh, stash in smem
    {
        const float* gpre = g_gates_pre + (size_t)t * B_ * G_;
        int c0 = 2 * tg;                    // local col within the 8
        int gc = ng + c0;                   // global gate col
        sg[r0][qg * 8 + c0]     = acc[0] + gpre[(size_t)r0 * G_ + gc]     + g_qghh[r0 * NA_ + H_ + gc];
        sg[r0][qg * 8 + c0 + 1] = acc[1] + gpre[(size_t)r0 * G_ + gc + 1] + g_qghh[r0 * NA_ + H_ + gc + 1];
        sg[r1][qg * 8 + c0]     = acc[2] + gpre[(size_t)r1 * G_ + gc]     + g_qghh[r1 * NA_ + H_ + gc];
        sg[r1][qg * 8 + c0 + 1] = acc[3] + gpre[(size_t)r1 * G_ + gc + 1] + g_qghh[r1 * NA_ + H_ + gc + 1];
    }
    __syncthreads();

    // LSTM update: 256 threads = 32 b x 8 j
    const int b = tid >> 3, jj = tid & 7;
    const int j = j0 + jj;
    float ig = 1.f / (1.f + expf(-sg[b][jj]));
    float fg = 1.f / (1.f + expf(-sg[b][8 + jj]));
    float gg = tanhf(sg[b][16 + jj]);
    float og = 1.f / (1.f + expf(-sg[b][24 + jj]));
    int par = t & 1;
    int idx = b * H_ + j;
    float c = fg * g_c[par][idx] + ig * gg;
    float h = og * tanhf(c);
    g_c[par ^ 1][idx] = c;
    g_h[par ^ 1][idx] = h;
    split_bf(h, g_ctxh_hi[b * 2048 + H_ + j], g_ctxh_lo[b * 2048 + H_ + j]);
    g_Hbf[(size_t)(t * B_ + b) * H_ + j] = __float2bfloat16(h);
}

// ------------------------- in-place log-softmax over V per output row -------------------------
__global__ void __launch_bounds__(256) k_logsoftmax(float* __restrict__ out) {
    __shared__ float red[8];
    __shared__ float bc;
    const int r = blockIdx.x;
    float* x = out + OUT_DEC + (size_t)r * V_;
    const int tid = threadIdx.x, lane = tid & 31, warp = tid >> 5;

    float m = -INFINITY;
    for (int v = tid; v < V_; v += 256) m = fmaxf(m, x[v]);
#pragma unroll
    for (int o2 = 16; o2; o2 >>= 1) m = fmaxf(m, __shfl_xor_sync(0xffffffffu, m, o2));
    if (lane == 0) red[warp] = m;
    __syncthreads();
    if (tid == 0) {
        float mm = red[0];
#pragma unroll
        for (int w = 1; w < 8; w++) mm = fmaxf(mm, red[w]);
        bc = mm;
    }
    __syncthreads();
    m = bc;

    float s = 0.f;
    for (int v = tid; v < V_; v += 256) s += expf(x[v] - m);
#pragma unroll
    for (int o2 = 16; o2; o2 >>= 1) s += __shfl_xor_sync(0xffffffffu, s, o2);
    __syncthreads();
    if (lane == 0) red[warp] = s;
    __syncthreads();
    if (tid == 0) {
        float ss = 0.f;
#pragma unroll
        for (int w = 0; w < 8; w++) ss += red[w];
        bc = m + logf(ss);
    }
    __syncthreads();
    float ls = bc;

    for (int v = tid; v < V_; v += 256) x[v] -= ls;
}

// ------------------------- final state copy -------------------------
__global__ void __launch_bounds__(256) k_final(float* __restrict__ out) {
    int i = blockIdx.x * blockDim.x + threadIdx.x;
    if (i < B_ * H_) {
        out[OUT_HF + i] = g_h[1][i];
        out[OUT_CF + i] = g_c[1][i];
    }
}

// ------------------------- launch -------------------------
extern "C" void kernel_launch(void* const* d_in, const int* in_sizes, int n_in,
                              void* d_out, int out_size) {
    (void)in_sizes; (void)n_in; (void)out_size;
    const float* enc  = (const float*)d_in[0];
    const float* ehid = (const float*)d_in[1];
    const int*   tgt  = (const int*)d_in[2];
    const float* emb  = (const float*)d_in[3];
    const float* Wq   = (const float*)d_in[4];
    const float* bq   = (const float*)d_in[5];
    const float* Wk   = (const float*)d_in[6];
    const float* bk   = (const float*)d_in[7];
    const float* Vw   = (const float*)d_in[8];
    const float* bV   = (const float*)d_in[9];
    const float* Wih  = (const float*)d_in[10];
    const float* Whh  = (const float*)d_in[11];
    const float* bih  = (const float*)d_in[12];
    const float* bhh  = (const float*)d_in[13];
    const float* Wout = (const float*)d_in[14];
    const float* bout = (const float*)d_in[15];
    float* out = (float*)d_out;

    void *p_enc_hi, *p_enc_lo, *p_Wk_hi, *p_Wk_lo, *p_Wqhh_hi, *p_Wqhh_lo,
         *p_Wx_hi, *p_Wx_lo, *p_Wout, *p_X_hi, *p_X_lo, *p_keys, *p_gpre,
         *p_qghh, *p_ch_hi, *p_ch_lo, *p_Hbf, *p_bsum, *p_bA;
    cudaGetSymbolAddress(&p_enc_hi, g_enc_hi);
    cudaGetSymbolAddress(&p_enc_lo, g_enc_lo);
    cudaGetSymbolAddress(&p_Wk_hi, g_Wk_hi);
    cudaGetSymbolAddress(&p_Wk_lo, g_Wk_lo);
    cudaGetSymbolAddress(&p_Wqhh_hi, g_Wqhh_hi);
    cudaGetSymbolAddress(&p_Wqhh_lo, g_Wqhh_lo);
    cudaGetSymbolAddress(&p_Wx_hi, g_Wx_hi);
    cudaGetSymbolAddress(&p_Wx_lo, g_Wx_lo);
    cudaGetSymbolAddress(&p_Wout, g_Wout_bf);
    cudaGetSymbolAddress(&p_X_hi, g_X_hi);
    cudaGetSymbolAddress(&p_X_lo, g_X_lo);
    cudaGetSymbolAddress(&p_keys, g_keys);
    cudaGetSymbolAddress(&p_gpre, g_gates_pre);
    cudaGetSymbolAddress(&p_qghh, g_qghh);
    cudaGetSymbolAddress(&p_ch_hi, g_ctxh_hi);
    cudaGetSymbolAddress(&p_ch_lo, g_ctxh_lo);
    cudaGetSymbolAddress(&p_Hbf, g_Hbf);
    cudaGetSymbolAddress(&p_bsum, g_bsum);
    cudaGetSymbolAddress(&p_bA, g_bA);

    // prep
    k_cvt2<<<2048, 256>>>(enc, (bf16*)p_enc_hi, (bf16*)p_enc_lo, TB_ * H_);
    k_transpose_enc<<<B_, 256>>>(enc);
    k_cvt2<<<1024, 256>>>(Wk, (bf16*)p_Wk_hi, (bf16*)p_Wk_lo, H_ * H_);
    k_cvt<<<4096, 256>>>(Wout, (bf16*)p_Wout, V_ * H_);
    k_wqhh<<<4096, 256>>>(Wq, Whh);
    k_cvt_wx<<<4096, 256>>>(Wih);
    k_wc<<<4096, 256>>>(Wih);
    k_bias<<<20, 256>>>(bih, bhh, bq);
    k_init<<<128, 256>>>(ehid);
    k_gather<<<TB_, 256>>>(emb, tgt);

    // hoisted GEMMs (split precision)
    {   // keys_proj = enc @ Wk^T + bk : [1312,1024]
        dim3 grid((TB_ + 63) / 64, H_ / 128);
        k_gemm2<4, 2, 8><<<grid, 256>>>((const bf16*)p_enc_hi, (const bf16*)p_enc_lo, H_,
                                        (const bf16*)p_Wk_hi, (const bf16*)p_Wk_lo, H_,
                                        (float*)p_keys, H_, bk, TB_, H_, H_);
    }
    {   // gates_pre = X @ Wx^T + (bih+bhh) : [1312,4096]
        dim3 grid((TB_ + 63) / 64, G_ / 128);
        k_gemm2<4, 2, 8><<<grid, 256>>>((const bf16*)p_X_hi, (const bf16*)p_X_lo, H_,
                                        (const bf16*)p_Wx_hi, (const bf16*)p_Wx_lo, H_,
                                        (float*)p_gpre, G_, (const float*)p_bsum, TB_, G_, H_);
    }

    // sequential decode: 3 launches per step
    for (int t = 0; t < T_; t++) {
        {   // [q | ghh] = h @ [Wq|Whh]^T + [bq|0] : [32, 5120], K=1024, 80 blocks
            dim3 grid(1, NA_ / 64);
            k_gemm2<2, 2, 4><<<grid, 128>>>((const bf16*)p_ch_hi + H_, (const bf16*)p_ch_lo + H_, 2 * H_,
                                            (const bf16*)p_Wqhh_hi, (const bf16*)p_Wqhh_lo, H_,
                                            (float*)p_qghh, NA_, (const float*)p_bA, B_, NA_, H_);
        }
        k_attn<<<B_, 256>>>(Vw, bV, out + OUT_ATTN, t);
        k_gates<<<128, 256>>>(t);
    }

    {   // logits -> directly into out[OUT_DEC] at [b,t,:] via remap epilogue
        dim3 grid((TB_ + 63) / 64, V_ / 128);
        k_gemm<4, 2, 8, true><<<grid, 256>>>((const bf16*)p_Hbf, H_, (const bf16*)p_Wout, H_,
                                             out + OUT_DEC, V_, bout, TB_, V_, H_);
    }
    k_logsoftmax<<<TB_, 256>>>(out);
    k_final<<<128, 256>>>(out);
}